// round 3
// baseline (speedup 1.0000x reference)
#include <cuda_runtime.h>
#include <cstdint>
#include <math.h>

#define BSZ     256
#define GRID_G  49
#define LSTMH   512
#define CNNC    2048
#define PROJ    512
#define M_TOTAL (BSZ * GRID_G)   /* 12544 */

// Scratch (no allocation allowed -> __device__ globals)
__device__ float g_H[BSZ * PROJ];     // H = lstm @ W_lstm^T + b_lstm   (full fp32)
__device__ float g_z[M_TOTAL];        // z logits before scramble+softmax

// ---------------------------------------------------------------------------
// Kernel 1: H GEMM (tiny: 256x512x512) + zero g_z
// BM=BN=32, BK=32, 256 threads, 2x2 microtile
// ---------------------------------------------------------------------------
__global__ __launch_bounds__(256) void h_gemm_kernel(
    const float* __restrict__ X,     // lstm_hidden (256,512)
    const float* __restrict__ W,     // W_lstm (512,512)
    const float* __restrict__ bias)  // b_lstm (512)
{
    __shared__ float As[32][33];
    __shared__ float Bs[32][33];
    const int t  = threadIdx.x;
    const int bx = blockIdx.x;   // m tile (8)
    const int by = blockIdx.y;   // n tile (16)
    const int mBase = bx * 32;
    const int nBase = by * 32;

    // zero z scratch (kernel ordering guarantees completion before kernel 2)
    int flat = (by * gridDim.x + bx) * 256 + t;
    if (flat < M_TOTAL) g_z[flat] = 0.0f;

    const int lrow = t >> 3;       // 0..31
    const int lf4  = (t & 7) * 4;  // 0..28 step 4
    const int ty   = t >> 4;       // 0..15
    const int tx   = t & 15;       // 0..15

    float acc[2][2] = {{0.f, 0.f}, {0.f, 0.f}};

    for (int k0 = 0; k0 < LSTMH; k0 += 32) {
        float4 a = *reinterpret_cast<const float4*>(X + (mBase + lrow) * LSTMH + k0 + lf4);
        float4 b = *reinterpret_cast<const float4*>(W + (nBase + lrow) * LSTMH + k0 + lf4);
        __syncthreads();
        As[lrow][lf4 + 0] = a.x; As[lrow][lf4 + 1] = a.y;
        As[lrow][lf4 + 2] = a.z; As[lrow][lf4 + 3] = a.w;
        Bs[lrow][lf4 + 0] = b.x; Bs[lrow][lf4 + 1] = b.y;
        Bs[lrow][lf4 + 2] = b.z; Bs[lrow][lf4 + 3] = b.w;
        __syncthreads();
        #pragma unroll
        for (int k = 0; k < 32; k++) {
            float a0 = As[ty * 2 + 0][k];
            float a1 = As[ty * 2 + 1][k];
            float b0 = Bs[tx * 2 + 0][k];
            float b1 = Bs[tx * 2 + 1][k];
            acc[0][0] += a0 * b0; acc[0][1] += a0 * b1;
            acc[1][0] += a1 * b0; acc[1][1] += a1 * b1;
        }
    }

    #pragma unroll
    for (int i = 0; i < 2; i++)
        #pragma unroll
        for (int j = 0; j < 2; j++) {
            int col = nBase + tx * 2 + j;
            g_H[(mBase + ty * 2 + i) * PROJ + col] = acc[i][j] + bias[col];
        }
}

// ---------------------------------------------------------------------------
// Kernel 2: fused V GEMM (tf32 mma) + bias + H + tanh + w-dot -> atomic z
// M=12544, N=512, K=2048.  BM=128, BN=128, BK=16.  256 thr = 8 warps (4M x 2N),
// warp tile 32x64 via m16n8k8.tf32 (2 m-tiles x 8 n-tiles, acc[2][8][4]).
// ---------------------------------------------------------------------------
__device__ __forceinline__ uint32_t f2tf(float f) {
    uint32_t u;
    asm("cvt.rna.tf32.f32 %0, %1;" : "=r"(u) : "f"(f));
    return u;
}

__device__ __forceinline__ uint4 ld_cvt(const float* p) {
    float4 v = *reinterpret_cast<const float4*>(p);
    uint4 r;
    r.x = f2tf(v.x); r.y = f2tf(v.y); r.z = f2tf(v.z); r.w = f2tf(v.w);
    return r;
}

__device__ __forceinline__ void mma_tf32(float c[4],
                                         const uint32_t a[4], const uint32_t b[2])
{
    asm volatile(
        "mma.sync.aligned.m16n8k8.row.col.f32.tf32.tf32.f32 "
        "{%0,%1,%2,%3}, {%4,%5,%6,%7}, {%8,%9}, {%0,%1,%2,%3};"
        : "+f"(c[0]), "+f"(c[1]), "+f"(c[2]), "+f"(c[3])
        : "r"(a[0]), "r"(a[1]), "r"(a[2]), "r"(a[3]), "r"(b[0]), "r"(b[1]));
}

#define SMP 20  /* smem row stride in floats: conflict-free & float4-aligned */

__global__ __launch_bounds__(256, 2) void attn_gemm_kernel(
    const float* __restrict__ A,      // cnn_feat (12544, 2048)
    const float* __restrict__ B,      // W_cnn   (512, 2048)
    const float* __restrict__ b_cnn,  // (512)
    const float* __restrict__ w_attn) // (512)
{
    __shared__ float As[128][SMP];
    __shared__ float Bs[128][SMP];

    const int t       = threadIdx.x;
    const int rowBase = blockIdx.x * 128;   // 98 tiles
    const int colBase = blockIdx.y * 128;   // 4 tiles
    const int wid  = t >> 5;
    const int lane = t & 31;
    const int g    = lane >> 2;  // groupID 0..7
    const int tig  = lane & 3;   // thread in group 0..3
    const int warpM = wid & 3;   // 0..3
    const int warpN = wid >> 2;  // 0..1

    float acc[2][8][4];
    #pragma unroll
    for (int mi = 0; mi < 2; mi++)
        #pragma unroll
        for (int ni = 0; ni < 8; ni++)
            #pragma unroll
            for (int c = 0; c < 4; c++) acc[mi][ni][c] = 0.0f;

    // loader: 512 float4 per operand tile; thread does rows lrow and lrow+64
    const int lrow = t >> 2;        // 0..63
    const int lk4  = (t & 3) * 4;   // 0,4,8,12
    const float* gA = A + (size_t)rowBase * CNNC;
    const float* gB = B + (size_t)colBase * CNNC;

    // preload stage 0
    uint4 pa0 = ld_cvt(gA + (size_t)lrow        * CNNC + lk4);
    uint4 pa1 = ld_cvt(gA + (size_t)(lrow + 64) * CNNC + lk4);
    uint4 pb0 = ld_cvt(gB + (size_t)lrow        * CNNC + lk4);
    uint4 pb1 = ld_cvt(gB + (size_t)(lrow + 64) * CNNC + lk4);
    *reinterpret_cast<uint4*>(&As[lrow][lk4])      = pa0;
    *reinterpret_cast<uint4*>(&As[lrow + 64][lk4]) = pa1;
    *reinterpret_cast<uint4*>(&Bs[lrow][lk4])      = pb0;
    *reinterpret_cast<uint4*>(&Bs[lrow + 64][lk4]) = pb1;
    __syncthreads();

    const int NSTAGE = CNNC / 16;  // 128
    for (int kt = 0; kt < NSTAGE; kt++) {
        if (kt < NSTAGE - 1) {
            int k0 = (kt + 1) * 16;
            pa0 = ld_cvt(gA + (size_t)lrow        * CNNC + k0 + lk4);
            pa1 = ld_cvt(gA + (size_t)(lrow + 64) * CNNC + k0 + lk4);
            pb0 = ld_cvt(gB + (size_t)lrow        * CNNC + k0 + lk4);
            pb1 = ld_cvt(gB + (size_t)(lrow + 64) * CNNC + k0 + lk4);
        }

        #pragma unroll
        for (int ks = 0; ks < 2; ks++) {
            uint32_t af[2][4];
            uint32_t bf[8][2];
            #pragma unroll
            for (int mi = 0; mi < 2; mi++) {
                int r0 = warpM * 32 + mi * 16 + g;
                af[mi][0] = __float_as_uint(As[r0    ][ks * 8 + tig]);
                af[mi][1] = __float_as_uint(As[r0 + 8][ks * 8 + tig]);
                af[mi][2] = __float_as_uint(As[r0    ][ks * 8 + tig + 4]);
                af[mi][3] = __float_as_uint(As[r0 + 8][ks * 8 + tig + 4]);
            }
            #pragma unroll
            for (int ni = 0; ni < 8; ni++) {
                int n0 = warpN * 64 + ni * 8 + g;
                bf[ni][0] = __float_as_uint(Bs[n0][ks * 8 + tig]);
                bf[ni][1] = __float_as_uint(Bs[n0][ks * 8 + tig + 4]);
            }
            #pragma unroll
            for (int mi = 0; mi < 2; mi++)
                #pragma unroll
                for (int ni = 0; ni < 8; ni++)
                    mma_tf32(acc[mi][ni], af[mi], bf[ni]);
        }

        if (kt < NSTAGE - 1) {
            __syncthreads();
            *reinterpret_cast<uint4*>(&As[lrow][lk4])      = pa0;
            *reinterpret_cast<uint4*>(&As[lrow + 64][lk4]) = pa1;
            *reinterpret_cast<uint4*>(&Bs[lrow][lk4])      = pb0;
            *reinterpret_cast<uint4*>(&Bs[lrow + 64][lk4]) = pb1;
            __syncthreads();
        }
    }

    // Epilogue: z[r] += sum_p tanh(V[r,p] + H[b,p] + b_cnn[p]) * w_attn[p]
    const int warpRow = rowBase + warpM * 32;
    const int warpCol = colBase + warpN * 64;
    #pragma unroll
    for (int mi = 0; mi < 2; mi++) {
        #pragma unroll
        for (int rh = 0; rh < 2; rh++) {
            int r = warpRow + mi * 16 + rh * 8 + g;
            int b = r / GRID_G;
            const float* Hrow = g_H + (size_t)b * PROJ;
            float s = 0.0f;
            #pragma unroll
            for (int ni = 0; ni < 8; ni++) {
                int p = warpCol + ni * 8 + tig * 2;
                float v0 = acc[mi][ni][rh * 2 + 0] + Hrow[p]     + __ldg(&b_cnn[p]);
                float v1 = acc[mi][ni][rh * 2 + 1] + Hrow[p + 1] + __ldg(&b_cnn[p + 1]);
                s += tanhf(v0) * __ldg(&w_attn[p]) + tanhf(v1) * __ldg(&w_attn[p + 1]);
            }
            s += __shfl_xor_sync(0xffffffffu, s, 1);
            s += __shfl_xor_sync(0xffffffffu, s, 2);
            if (tig == 0) atomicAdd(&g_z[r], s);
        }
    }
}

// ---------------------------------------------------------------------------
// Kernel 3: scramble + row softmax
// z_scr[i,j] = z[(i*49+j)%256, (i*49+j)/256];  softmax over j.
// ---------------------------------------------------------------------------
__global__ __launch_bounds__(64) void softmax_kernel(float* __restrict__ out)
{
    __shared__ float red[64];
    const int i = blockIdx.x;   // 0..255
    const int t = threadIdx.x;  // 0..63

    float v = -INFINITY;
    if (t < GRID_G) {
        int k = i * GRID_G + t;
        v = g_z[(k % BSZ) * GRID_G + (k / BSZ)];
    }
    red[t] = v;
    __syncthreads();
    #pragma unroll
    for (int s = 32; s > 0; s >>= 1) {
        if (t < s) red[t] = fmaxf(red[t], red[t + s]);
        __syncthreads();
    }
    float mx = red[0];
    __syncthreads();

    float e = (t < GRID_G) ? expf(v - mx) : 0.0f;
    red[t] = e;
    __syncthreads();
    #pragma unroll
    for (int s = 32; s > 0; s >>= 1) {
        if (t < s) red[t] += red[t + s];
        __syncthreads();
    }
    float sum = red[0];
    if (t < GRID_G) out[i * GRID_G + t] = e / sum;
}

// ---------------------------------------------------------------------------
extern "C" void kernel_launch(void* const* d_in, const int* in_sizes, int n_in,
                              void* d_out, int out_size)
{
    const float* lstm = (const float*)d_in[0];  // (256,512)
    const float* cnn  = (const float*)d_in[1];  // (256,49,2048)
    const float* Wl   = (const float*)d_in[2];  // (512,512)
    const float* bl   = (const float*)d_in[3];  // (512)
    const float* Wc   = (const float*)d_in[4];  // (512,2048)
    const float* bc   = (const float*)d_in[5];  // (512)
    const float* wa   = (const float*)d_in[6];  // (1,512)
    float* out = (float*)d_out;                 // (256,49)

    h_gemm_kernel<<<dim3(8, 16), 256>>>(lstm, Wl, bl);
    attn_gemm_kernel<<<dim3(98, 4), 256>>>(cnn, Wc, bc, wa);
    softmax_kernel<<<256, 64>>>(out);
}

// round 8
// speedup vs baseline: 1.2007x; 1.2007x over previous
#include <cuda_runtime.h>
#include <cuda_fp16.h>
#include <cstdint>
#include <math.h>

#define BSZ     256
#define GRID_G  49
#define LSTMH   512
#define CNNC    2048
#define PROJ    512
#define M_TOTAL (BSZ * GRID_G)   /* 12544 */

// Scratch (no allocation allowed -> __device__ globals)
__device__ float g_H[BSZ * PROJ];     // H' = lstm @ W_lstm^T + b_lstm + b_cnn
__device__ float g_z[M_TOTAL];        // z logits before scramble+softmax

// ===========================================================================
// Kernel 1: H' GEMM (256x512x512) + fold both biases + zero g_z
// ===========================================================================
__global__ __launch_bounds__(256) void h_gemm_kernel(
    const float* __restrict__ X,
    const float* __restrict__ W,
    const float* __restrict__ bl,
    const float* __restrict__ bc)
{
    __shared__ float As[32 * 129];
    __shared__ float Bs[32 * 129];
    const int t  = threadIdx.x;
    const int mBase = blockIdx.x * 32;   // 8
    const int nBase = blockIdx.y * 32;   // 16

    int flat = (blockIdx.y * gridDim.x + blockIdx.x) * 256 + t;
    if (flat < M_TOTAL) g_z[flat] = 0.0f;

    const int row = t >> 3;       // 0..31
    const int fc  = t & 7;        // float4 group
    const int ty  = t >> 4;       // 0..15
    const int tx  = t & 15;       // 0..15

    const float* xp = X + (size_t)(mBase + row) * LSTMH;
    const float* wp = W + (size_t)(nBase + row) * LSTMH;

    float acc[2][2] = {{0.f, 0.f}, {0.f, 0.f}};
    float4 pa[4], pb[4];

    #pragma unroll
    for (int i = 0; i < 4; i++) {
        pa[i] = *reinterpret_cast<const float4*>(xp + (fc + 8 * i) * 4);
        pb[i] = *reinterpret_cast<const float4*>(wp + (fc + 8 * i) * 4);
    }

    for (int c = 0; c < 4; c++) {
        if (c) __syncthreads();
        #pragma unroll
        for (int i = 0; i < 4; i++) {
            int base = row * 129 + (fc + 8 * i) * 4;
            As[base + 0] = pa[i].x; As[base + 1] = pa[i].y;
            As[base + 2] = pa[i].z; As[base + 3] = pa[i].w;
            Bs[base + 0] = pb[i].x; Bs[base + 1] = pb[i].y;
            Bs[base + 2] = pb[i].z; Bs[base + 3] = pb[i].w;
        }
        __syncthreads();
        if (c < 3) {
            int k0 = (c + 1) * 128;
            #pragma unroll
            for (int i = 0; i < 4; i++) {
                pa[i] = *reinterpret_cast<const float4*>(xp + k0 + (fc + 8 * i) * 4);
                pb[i] = *reinterpret_cast<const float4*>(wp + k0 + (fc + 8 * i) * 4);
            }
        }
        #pragma unroll 8
        for (int k = 0; k < 128; k++) {
            float a0 = As[(ty * 2 + 0) * 129 + k];
            float a1 = As[(ty * 2 + 1) * 129 + k];
            float b0 = Bs[(tx * 2 + 0) * 129 + k];
            float b1 = Bs[(tx * 2 + 1) * 129 + k];
            acc[0][0] += a0 * b0; acc[0][1] += a0 * b1;
            acc[1][0] += a1 * b0; acc[1][1] += a1 * b1;
        }
    }

    #pragma unroll
    for (int i = 0; i < 2; i++)
        #pragma unroll
        for (int j = 0; j < 2; j++) {
            int col = nBase + tx * 2 + j;
            g_H[(size_t)(mBase + ty * 2 + i) * PROJ + col] = acc[i][j] + bl[col] + bc[col];
        }
}

// ===========================================================================
// Kernel 2: fp16 mma.sync m16n8k16 GEMM + fused epilogue
// BM=128, BN=128, k-stage = 16 floats. 256 thr = 8 warps (2M x 4N),
// warp tile 64x32 = 4 m16-tiles x 4 n8-tiles. Double-buffered smem (1 bar/stage),
// register prefetch with on-the-fly f32->f16x2 conversion, ldmatrix.x4 fragments.
// grid (4, 98): col tile fastest so A row-tiles are L2-resident across col CTAs.
// ===========================================================================
#define SROW 24   /* halves per smem row (16 data + 8 pad): conflict-free for ldmatrix */

__device__ __forceinline__ void ldsm_x4(uint32_t& r0, uint32_t& r1,
                                        uint32_t& r2, uint32_t& r3, uint32_t addr)
{
    asm volatile("ldmatrix.sync.aligned.m8n8.x4.shared.b16 {%0,%1,%2,%3}, [%4];"
                 : "=r"(r0), "=r"(r1), "=r"(r2), "=r"(r3) : "r"(addr));
}

__device__ __forceinline__ void mma_f16(float c[4], const uint32_t a[4], const uint32_t b[2])
{
    asm volatile(
        "mma.sync.aligned.m16n8k16.row.col.f32.f16.f16.f32 "
        "{%0,%1,%2,%3}, {%4,%5,%6,%7}, {%8,%9}, {%0,%1,%2,%3};"
        : "+f"(c[0]), "+f"(c[1]), "+f"(c[2]), "+f"(c[3])
        : "r"(a[0]), "r"(a[1]), "r"(a[2]), "r"(a[3]), "r"(b[0]), "r"(b[1]));
}

__device__ __forceinline__ uint32_t pack_h2(float lo, float hi) {
    __half2 h = __floats2half2_rn(lo, hi);
    return *reinterpret_cast<uint32_t*>(&h);
}

__device__ __forceinline__ float tanh_ap(float x) {
    float y;
    asm("tanh.approx.f32 %0, %1;" : "=f"(y) : "f"(x));
    return y;
}

#define BUF_HALVES (128 * SROW)          /* per-buffer halves = 3072 (6144 B) */

__global__ __launch_bounds__(256, 2) void attn_gemm_kernel(
    const float* __restrict__ A,      // cnn_feat (12544, 2048)
    const float* __restrict__ B,      // W_cnn    (512, 2048)
    const float* __restrict__ w_attn) // (512)
{
    __shared__ __align__(16) __half As[2 * BUF_HALVES];
    __shared__ __align__(16) __half Bs[2 * BUF_HALVES];

    const int t       = threadIdx.x;
    const int lane    = t & 31;
    const int wid     = t >> 5;
    const int warpM   = wid >> 2;           // 0..1  -> 64 rows
    const int warpN   = wid & 3;            // 0..3  -> 32 cols
    const int colBase = blockIdx.x * 128;   // 4 col tiles (fastest)
    const int rowBase = blockIdx.y * 128;   // 98 row tiles

    const uint32_t aSm = (uint32_t)__cvta_generic_to_shared(As);
    const uint32_t bSm = (uint32_t)__cvta_generic_to_shared(Bs);

    // ldmatrix per-lane byte offsets (constant across stages)
    // A x4 (one m16k16 tile): lanes0-7 rows m+0..7 @k0, 8-15 rows m+8..15 @k0,
    //                         16-23 rows m+0..7 @k8, 24-31 rows m+8..15 @k8
    uint32_t offA[4];
    #pragma unroll
    for (int mi = 0; mi < 4; mi++) {
        int r = warpM * 64 + mi * 16 + (lane & 15);
        int kq = ((lane >> 4) & 1) * 8;
        offA[mi] = (uint32_t)((r * SROW + kq) * 2);
    }
    // B x4 (two n8k16 tiles): lanes0-7 n+0..7 @k0, 8-15 n+0..7 @k8,
    //                         16-23 n+8..15 @k0, 24-31 n+8..15 @k8
    uint32_t offB[2];
    #pragma unroll
    for (int np = 0; np < 2; np++) {
        int r = warpN * 32 + np * 16 + ((lane >> 4) & 1) * 8 + (lane & 7);
        int kq = ((lane >> 3) & 1) * 8;
        offB[np] = (uint32_t)((r * SROW + kq) * 2);
    }

    float acc[4][4][4];
    #pragma unroll
    for (int mi = 0; mi < 4; mi++)
        #pragma unroll
        for (int ni = 0; ni < 4; ni++)
            #pragma unroll
            for (int c = 0; c < 4; c++) acc[mi][ni][c] = 0.0f;

    // Loader mapping: thread covers one smem row-half:
    // row = t>>1 (0..127), f4 = (t&1)*2 + j (j=0,1) -> k floats f4*4..+3
    const int lrow = t >> 1;
    const int lhalf = t & 1;
    const float* gA = A + (size_t)(rowBase + lrow) * CNNC + lhalf * 8;
    const float* gB = B + (size_t)(colBase + lrow) * CNNC + lhalf * 8;
    uint2* As2 = reinterpret_cast<uint2*>(As);   // 6 uint2 per row (SROW*2/8)
    uint2* Bs2 = reinterpret_cast<uint2*>(Bs);
    const int sIdxBase = lrow * (SROW / 4) + lhalf * 2;   // uint2 index

    float4 pa[2], pb[2];

    // preload stage 0
    #pragma unroll
    for (int j = 0; j < 2; j++) {
        pa[j] = *reinterpret_cast<const float4*>(gA + j * 4);
        pb[j] = *reinterpret_cast<const float4*>(gB + j * 4);
    }
    #pragma unroll
    for (int j = 0; j < 2; j++) {
        As2[sIdxBase + j] = make_uint2(pack_h2(pa[j].x, pa[j].y), pack_h2(pa[j].z, pa[j].w));
        Bs2[sIdxBase + j] = make_uint2(pack_h2(pb[j].x, pb[j].y), pack_h2(pb[j].z, pb[j].w));
    }
    __syncthreads();

    const int NSTG = CNNC / 16;   // 128
    int buf = 0;

    for (int kt = 0; kt < NSTG; kt++) {
        // prefetch next stage (global f32)
        if (kt + 1 < NSTG) {
            const float* pA = gA + (size_t)(kt + 1) * 16;
            const float* pB = gB + (size_t)(kt + 1) * 16;
            #pragma unroll
            for (int j = 0; j < 2; j++) {
                pa[j] = *reinterpret_cast<const float4*>(pA + j * 4);
                pb[j] = *reinterpret_cast<const float4*>(pB + j * 4);
            }
        }

        // compute current stage from buf
        {
            const uint32_t aBase = aSm + buf * (BUF_HALVES * 2);
            const uint32_t bBase = bSm + buf * (BUF_HALVES * 2);
            uint32_t af[4][4];
            uint32_t bf[4][2];
            #pragma unroll
            for (int mi = 0; mi < 4; mi++)
                ldsm_x4(af[mi][0], af[mi][1], af[mi][2], af[mi][3], aBase + offA[mi]);
            #pragma unroll
            for (int np = 0; np < 2; np++) {
                uint32_t r0, r1, r2, r3;
                ldsm_x4(r0, r1, r2, r3, bBase + offB[np]);
                bf[np * 2 + 0][0] = r0; bf[np * 2 + 0][1] = r1;
                bf[np * 2 + 1][0] = r2; bf[np * 2 + 1][1] = r3;
            }
            #pragma unroll
            for (int mi = 0; mi < 4; mi++)
                #pragma unroll
                for (int ni = 0; ni < 4; ni++)
                    mma_f16(acc[mi][ni], af[mi], bf[ni]);
        }

        // store prefetched stage into other buffer, one barrier per stage
        if (kt + 1 < NSTG) {
            int nb = buf ^ 1;
            int base = nb * (BUF_HALVES / 4) + sIdxBase;   // uint2 index offset
            #pragma unroll
            for (int j = 0; j < 2; j++) {
                As2[base + j] = make_uint2(pack_h2(pa[j].x, pa[j].y), pack_h2(pa[j].z, pa[j].w));
                Bs2[base + j] = make_uint2(pack_h2(pb[j].x, pb[j].y), pack_h2(pb[j].z, pb[j].w));
            }
        }
        __syncthreads();
        buf ^= 1;
    }

    // Epilogue: z[r] += sum_p tanh(V[r,p] + H'[b,p]) * w_attn[p]
    // acc thread layout: c0,c1 = (row lane>>2, cols 2tig,2tig+1); c2,c3 = row+8
    const int tig = lane & 3;
    const float* wcol = w_attn + colBase + warpN * 32;
    #pragma unroll
    for (int mi = 0; mi < 4; mi++) {
        #pragma unroll
        for (int h = 0; h < 2; h++) {
            int r = rowBase + warpM * 64 + mi * 16 + h * 8 + (lane >> 2);
            int bidx = r / GRID_G;
            const float* Hrow = g_H + (size_t)bidx * PROJ + colBase + warpN * 32;
            float s = 0.0f;
            #pragma unroll
            for (int ni = 0; ni < 4; ni++) {
                int p = ni * 8 + tig * 2;
                float v0 = acc[mi][ni][h * 2 + 0] + __ldg(Hrow + p);
                float v1 = acc[mi][ni][h * 2 + 1] + __ldg(Hrow + p + 1);
                s += tanh_ap(v0) * __ldg(wcol + p) + tanh_ap(v1) * __ldg(wcol + p + 1);
            }
            s += __shfl_xor_sync(0xffffffffu, s, 1);
            s += __shfl_xor_sync(0xffffffffu, s, 2);
            if (tig == 0) atomicAdd(&g_z[r], s);
        }
    }
}

// ===========================================================================
// Kernel 3: scramble + row softmax
// ===========================================================================
__global__ __launch_bounds__(64) void softmax_kernel(float* __restrict__ out)
{
    __shared__ float red[64];
    const int i = blockIdx.x;
    const int t = threadIdx.x;

    float v = -INFINITY;
    if (t < GRID_G) {
        int k = i * GRID_G + t;
        v = g_z[(k % BSZ) * GRID_G + (k / BSZ)];
    }
    red[t] = v;
    __syncthreads();
    #pragma unroll
    for (int s = 32; s > 0; s >>= 1) {
        if (t < s) red[t] = fmaxf(red[t], red[t + s]);
        __syncthreads();
    }
    float mx = red[0];
    __syncthreads();

    float e = (t < GRID_G) ? expf(v - mx) : 0.0f;
    red[t] = e;
    __syncthreads();
    #pragma unroll
    for (int s = 32; s > 0; s >>= 1) {
        if (t < s) red[t] += red[t + s];
        __syncthreads();
    }
    float sum = red[0];
    if (t < GRID_G) out[i * GRID_G + t] = e / sum;
}

// ===========================================================================
extern "C" void kernel_launch(void* const* d_in, const int* in_sizes, int n_in,
                              void* d_out, int out_size)
{
    const float* lstm = (const float*)d_in[0];  // (256,512)
    const float* cnn  = (const float*)d_in[1];  // (256,49,2048)
    const float* Wl   = (const float*)d_in[2];  // (512,512)
    const float* bl   = (const float*)d_in[3];  // (512)
    const float* Wc   = (const float*)d_in[4];  // (512,2048)
    const float* bc   = (const float*)d_in[5];  // (512)
    const float* wa   = (const float*)d_in[6];  // (1,512)
    float* out = (float*)d_out;                 // (256,49)

    h_gemm_kernel<<<dim3(8, 16), 256>>>(lstm, Wl, bl, bc);
    attn_gemm_kernel<<<dim3(4, 98), 256>>>(cnn, Wc, wa);
    softmax_kernel<<<256, 64>>>(out);
}

// round 9
// speedup vs baseline: 2.1790x; 1.8147x over previous
#include <cuda_runtime.h>
#include <cuda_fp16.h>
#include <cstdint>
#include <math.h>

#define BSZ     256
#define GRID_G  49
#define LSTMH   512
#define CNNC    2048
#define PROJ    512
#define M_TOTAL (BSZ * GRID_G)   /* 12544 */

#define A_ELEMS (M_TOTAL * CNNC)  /* 25,690,112 */
#define B_ELEMS (PROJ * CNNC)     /* 1,048,576  */

// Scratch (no allocation allowed -> __device__ globals)
__device__ float g_H[BSZ * PROJ];                 // H' = lstm@Wl^T + bl + bc
__device__ float g_z[M_TOTAL];                    // logits
__device__ __align__(16) __half g_Af16[A_ELEMS];  // cnn_feat in fp16 (51MB, L2-resident)
__device__ __align__(16) __half g_Bf16[B_ELEMS];  // W_cnn   in fp16 (2MB)

__device__ __forceinline__ uint32_t pack_h2(float lo, float hi) {
    __half2 h = __floats2half2_rn(lo, hi);
    return *reinterpret_cast<uint32_t*>(&h);
}
__device__ __forceinline__ float tanh_ap(float x) {
    float y;
    asm("tanh.approx.f32 %0, %1;" : "=f"(y) : "f"(x));
    return y;
}

// ===========================================================================
// Kernel 1 (prep): blocks 0..127 compute H' (32x32 tiles) + zero g_z;
// blocks 128.. convert cnn_feat / W_cnn to fp16 (grid-stride-free 1:1 map).
// The tiny H GEMM hides under the conversion's DRAM streaming.
// ===========================================================================
#define H_BLOCKS 128
#define ACH (A_ELEMS / 8)          /* 3,211,264 conversion chunks (8 floats) */
#define BCH (B_ELEMS / 8)          /* 131,072 */
#define CONV_BLOCKS ((ACH + BCH + 255) / 256)   /* 13,056 */

__global__ __launch_bounds__(256) void prep_kernel(
    const float* __restrict__ X,     // lstm_hidden
    const float* __restrict__ W,     // W_lstm
    const float* __restrict__ bl,
    const float* __restrict__ bc,
    const float* __restrict__ A,     // cnn_feat f32
    const float* __restrict__ Bw)    // W_cnn f32
{
    __shared__ float As[32 * 129];
    __shared__ float Bs[32 * 129];
    const int t = threadIdx.x;

    if (blockIdx.x >= H_BLOCKS) {
        // ---- conversion part ----
        long idx8 = (long)(blockIdx.x - H_BLOCKS) * 256 + t;
        if (idx8 < ACH) {
            const float* src = A + idx8 * 8;
            float4 v0 = *reinterpret_cast<const float4*>(src);
            float4 v1 = *reinterpret_cast<const float4*>(src + 4);
            *reinterpret_cast<uint4*>(g_Af16 + idx8 * 8) =
                make_uint4(pack_h2(v0.x, v0.y), pack_h2(v0.z, v0.w),
                           pack_h2(v1.x, v1.y), pack_h2(v1.z, v1.w));
        } else if (idx8 < ACH + BCH) {
            long j = idx8 - ACH;
            const float* src = Bw + j * 8;
            float4 v0 = *reinterpret_cast<const float4*>(src);
            float4 v1 = *reinterpret_cast<const float4*>(src + 4);
            *reinterpret_cast<uint4*>(g_Bf16 + j * 8) =
                make_uint4(pack_h2(v0.x, v0.y), pack_h2(v0.z, v0.w),
                           pack_h2(v1.x, v1.y), pack_h2(v1.z, v1.w));
        }
        return;
    }

    // ---- H' GEMM part (blocks 0..127) ----
    const int hb = blockIdx.x;
    const int mBase = (hb & 7) * 32;    // 8 m tiles
    const int nBase = (hb >> 3) * 32;   // 16 n tiles

    int flat = hb * 256 + t;
    if (flat < M_TOTAL) g_z[flat] = 0.0f;

    const int row = t >> 3;
    const int fc  = t & 7;
    const int ty  = t >> 4;
    const int tx  = t & 15;

    const float* xp = X + (size_t)(mBase + row) * LSTMH;
    const float* wp = W + (size_t)(nBase + row) * LSTMH;

    float acc[2][2] = {{0.f, 0.f}, {0.f, 0.f}};
    float4 pa[4], pb[4];

    #pragma unroll
    for (int i = 0; i < 4; i++) {
        pa[i] = *reinterpret_cast<const float4*>(xp + (fc + 8 * i) * 4);
        pb[i] = *reinterpret_cast<const float4*>(wp + (fc + 8 * i) * 4);
    }

    for (int c = 0; c < 4; c++) {
        if (c) __syncthreads();
        #pragma unroll
        for (int i = 0; i < 4; i++) {
            int base = row * 129 + (fc + 8 * i) * 4;
            As[base + 0] = pa[i].x; As[base + 1] = pa[i].y;
            As[base + 2] = pa[i].z; As[base + 3] = pa[i].w;
            Bs[base + 0] = pb[i].x; Bs[base + 1] = pb[i].y;
            Bs[base + 2] = pb[i].z; Bs[base + 3] = pb[i].w;
        }
        __syncthreads();
        if (c < 3) {
            int k0 = (c + 1) * 128;
            #pragma unroll
            for (int i = 0; i < 4; i++) {
                pa[i] = *reinterpret_cast<const float4*>(xp + k0 + (fc + 8 * i) * 4);
                pb[i] = *reinterpret_cast<const float4*>(wp + k0 + (fc + 8 * i) * 4);
            }
        }
        #pragma unroll 8
        for (int k = 0; k < 128; k++) {
            float a0 = As[(ty * 2 + 0) * 129 + k];
            float a1 = As[(ty * 2 + 1) * 129 + k];
            float b0 = Bs[(tx * 2 + 0) * 129 + k];
            float b1 = Bs[(tx * 2 + 1) * 129 + k];
            acc[0][0] += a0 * b0; acc[0][1] += a0 * b1;
            acc[1][0] += a1 * b0; acc[1][1] += a1 * b1;
        }
    }

    #pragma unroll
    for (int i = 0; i < 2; i++)
        #pragma unroll
        for (int j = 0; j < 2; j++) {
            int col = nBase + tx * 2 + j;
            g_H[(size_t)(mBase + ty * 2 + i) * PROJ + col] = acc[i][j] + bl[col] + bc[col];
        }
}

// ===========================================================================
// Kernel 2: fp16 mma m16n8k16, cp.async 3-slot ring, K-chunk 32 halves.
// BM=BN=128, 8 warps (2M x 4N), warp tile 64x32, ldmatrix.x4 fragments.
// grid (4, 98): col tile fastest; A (51MB fp16) is L2-resident across reuse.
// ===========================================================================
#define SROWB  80                        /* bytes per smem row: 64 data + 16 pad */
#define STG_B  (2 * 128 * SROWB)         /* A+B per stage = 20480 B */
#define NRING  3
#define ATT_SMEM (NRING * STG_B)         /* 61440 B */
#define NSTG   (CNNC / 32)               /* 64 */

__device__ __forceinline__ void ldsm_x4(uint32_t& r0, uint32_t& r1,
                                        uint32_t& r2, uint32_t& r3, uint32_t addr)
{
    asm volatile("ldmatrix.sync.aligned.m8n8.x4.shared.b16 {%0,%1,%2,%3}, [%4];"
                 : "=r"(r0), "=r"(r1), "=r"(r2), "=r"(r3) : "r"(addr));
}
__device__ __forceinline__ void mma_f16(float c[4], const uint32_t a[4], const uint32_t b[2])
{
    asm volatile(
        "mma.sync.aligned.m16n8k16.row.col.f32.f16.f16.f32 "
        "{%0,%1,%2,%3}, {%4,%5,%6,%7}, {%8,%9}, {%0,%1,%2,%3};"
        : "+f"(c[0]), "+f"(c[1]), "+f"(c[2]), "+f"(c[3])
        : "r"(a[0]), "r"(a[1]), "r"(a[2]), "r"(a[3]), "r"(b[0]), "r"(b[1]));
}
__device__ __forceinline__ void cp_async16(uint32_t sdst, const void* gsrc) {
    asm volatile("cp.async.cg.shared.global [%0], [%1], 16;" :: "r"(sdst), "l"(gsrc) : "memory");
}
__device__ __forceinline__ void cp_commit() { asm volatile("cp.async.commit_group;" ::: "memory"); }
__device__ __forceinline__ void cp_wait1()  { asm volatile("cp.async.wait_group 1;"  ::: "memory"); }

__global__ __launch_bounds__(256, 2) void attn_gemm_kernel(
    const float* __restrict__ w_attn) // (512)
{
    extern __shared__ __align__(16) char smem[];
    const uint32_t sb = (uint32_t)__cvta_generic_to_shared(smem);

    const int t       = threadIdx.x;
    const int lane    = t & 31;
    const int wid     = t >> 5;
    const int warpM   = wid >> 2;           // 0..1
    const int warpN   = wid & 3;            // 0..3
    const int colBase = blockIdx.x * 128;   // 4 (fastest)
    const int rowBase = blockIdx.y * 128;   // 98

    // ldmatrix per-lane byte offsets (add slot base + ks*32 at use)
    uint32_t offA[4];
    #pragma unroll
    for (int mi = 0; mi < 4; mi++) {
        int r = warpM * 64 + mi * 16 + (lane & 15);
        offA[mi] = (uint32_t)(r * SROWB + ((lane >> 4) & 1) * 16);
    }
    uint32_t offB[2];
    #pragma unroll
    for (int np = 0; np < 2; np++) {
        int r = warpN * 32 + np * 16 + ((lane >> 4) & 1) * 8 + (lane & 7);
        offB[np] = (uint32_t)(r * SROWB + ((lane >> 3) & 1) * 16);
    }

    float acc[4][4][4];
    #pragma unroll
    for (int mi = 0; mi < 4; mi++)
        #pragma unroll
        for (int ni = 0; ni < 4; ni++)
            #pragma unroll
            for (int c = 0; c < 4; c++) acc[mi][ni][c] = 0.0f;

    // loader: row = t>>1 (0..127), two 16B chunks per matrix per stage
    const int lrow = t >> 1;
    const int lq   = (t & 1) * 2;
    const __half* gA = g_Af16 + (size_t)(rowBase + lrow) * CNNC;
    const __half* gB = g_Bf16 + (size_t)(colBase + lrow) * CNNC;
    const uint32_t dstRow = (uint32_t)(lrow * SROWB);

    auto load_stage = [&](int slot, int kt) {
        uint32_t base = sb + slot * STG_B;
        #pragma unroll
        for (int j = 0; j < 2; j++) {
            int ch = lq + j;                      // 0..3
            uint32_t d = dstRow + ch * 16;
            const __half* sA = gA + kt * 32 + ch * 8;
            const __half* sB = gB + kt * 32 + ch * 8;
            cp_async16(base + d, sA);
            cp_async16(base + 128 * SROWB + d, sB);
        }
    };

    // prologue: slots 0,1
    load_stage(0, 0); cp_commit();
    load_stage(1, 1); cp_commit();

    for (int kt = 0; kt < NSTG; kt++) {
        cp_wait1();            // slot kt resident (only newest group may pend)
        __syncthreads();       // orders prior compute before refill of this slot

        if (kt + 2 < NSTG) load_stage((kt + 2) % NRING, kt + 2);
        cp_commit();

        const uint32_t aBase = sb + (kt % NRING) * STG_B;
        const uint32_t bBase = aBase + 128 * SROWB;
        #pragma unroll
        for (int ks = 0; ks < 2; ks++) {
            uint32_t af[4][4];
            uint32_t bf[4][2];
            #pragma unroll
            for (int mi = 0; mi < 4; mi++)
                ldsm_x4(af[mi][0], af[mi][1], af[mi][2], af[mi][3],
                        aBase + offA[mi] + ks * 32);
            #pragma unroll
            for (int np = 0; np < 2; np++) {
                uint32_t r0, r1, r2, r3;
                ldsm_x4(r0, r1, r2, r3, bBase + offB[np] + ks * 32);
                bf[np * 2 + 0][0] = r0; bf[np * 2 + 0][1] = r1;
                bf[np * 2 + 1][0] = r2; bf[np * 2 + 1][1] = r3;
            }
            #pragma unroll
            for (int mi = 0; mi < 4; mi++)
                #pragma unroll
                for (int ni = 0; ni < 4; ni++)
                    mma_f16(acc[mi][ni], af[mi], bf[ni]);
        }
    }

    // Epilogue: z[r] += sum_p tanh(V[r,p] + H'[b,p]) * w_attn[p]
    const int tig = lane & 3;
    const float* wcol = w_attn + colBase + warpN * 32;
    #pragma unroll
    for (int mi = 0; mi < 4; mi++) {
        #pragma unroll
        for (int h = 0; h < 2; h++) {
            int r = rowBase + warpM * 64 + mi * 16 + h * 8 + (lane >> 2);
            int bidx = r / GRID_G;
            const float* Hrow = g_H + (size_t)bidx * PROJ + colBase + warpN * 32;
            float s = 0.0f;
            #pragma unroll
            for (int ni = 0; ni < 4; ni++) {
                int p = ni * 8 + tig * 2;
                float v0 = acc[mi][ni][h * 2 + 0] + __ldg(Hrow + p);
                float v1 = acc[mi][ni][h * 2 + 1] + __ldg(Hrow + p + 1);
                s += tanh_ap(v0) * __ldg(wcol + p) + tanh_ap(v1) * __ldg(wcol + p + 1);
            }
            s += __shfl_xor_sync(0xffffffffu, s, 1);
            s += __shfl_xor_sync(0xffffffffu, s, 2);
            if (tig == 0) atomicAdd(&g_z[r], s);
        }
    }
}

// ===========================================================================
// Kernel 3: scramble + row softmax
// ===========================================================================
__global__ __launch_bounds__(64) void softmax_kernel(float* __restrict__ out)
{
    __shared__ float red[64];
    const int i = blockIdx.x;
    const int t = threadIdx.x;

    float v = -INFINITY;
    if (t < GRID_G) {
        int k = i * GRID_G + t;
        v = g_z[(k % BSZ) * GRID_G + (k / BSZ)];
    }
    red[t] = v;
    __syncthreads();
    #pragma unroll
    for (int s = 32; s > 0; s >>= 1) {
        if (t < s) red[t] = fmaxf(red[t], red[t + s]);
        __syncthreads();
    }
    float mx = red[0];
    __syncthreads();

    float e = (t < GRID_G) ? expf(v - mx) : 0.0f;
    red[t] = e;
    __syncthreads();
    #pragma unroll
    for (int s = 32; s > 0; s >>= 1) {
        if (t < s) red[t] += red[t + s];
        __syncthreads();
    }
    float sum = red[0];
    if (t < GRID_G) out[i * GRID_G + t] = e / sum;
}

// ===========================================================================
extern "C" void kernel_launch(void* const* d_in, const int* in_sizes, int n_in,
                              void* d_out, int out_size)
{
    const float* lstm = (const float*)d_in[0];  // (256,512)
    const float* cnn  = (const float*)d_in[1];  // (256,49,2048)
    const float* Wl   = (const float*)d_in[2];  // (512,512)
    const float* bl   = (const float*)d_in[3];  // (512)
    const float* Wc   = (const float*)d_in[4];  // (512,2048)
    const float* bc   = (const float*)d_in[5];  // (512)
    const float* wa   = (const float*)d_in[6];  // (1,512)
    float* out = (float*)d_out;                 // (256,49)

    cudaFuncSetAttribute(attn_gemm_kernel,
                         cudaFuncAttributeMaxDynamicSharedMemorySize, ATT_SMEM);

    prep_kernel<<<H_BLOCKS + CONV_BLOCKS, 256>>>(lstm, Wl, bl, bc, cnn, Wc);
    attn_gemm_kernel<<<dim3(4, 98), 256, ATT_SMEM>>>(wa);
    softmax_kernel<<<256, 64>>>(out);
}

// round 10
// speedup vs baseline: 2.8515x; 1.3086x over previous
#include <cuda_runtime.h>
#include <cuda_fp16.h>
#include <cstdint>
#include <math.h>

#define BSZ     256
#define GRID_G  49
#define LSTMH   512
#define CNNC    2048
#define PROJ    512
#define M_TOTAL (BSZ * GRID_G)   /* 12544 */

#define A_ELEMS (M_TOTAL * CNNC)  /* 25,690,112 */
#define B_ELEMS (PROJ * CNNC)     /* 1,048,576  */

// Scratch (no allocation allowed -> __device__ globals)
__device__ float g_H[BSZ * PROJ];                 // H' = lstm@Wl^T + bl + bc
__device__ float g_z[M_TOTAL];                    // logits
__device__ __align__(16) __half g_Af16[A_ELEMS];  // cnn_feat fp16 (51MB, L2-resident)
__device__ __align__(16) __half g_Bf16[B_ELEMS];  // W_cnn fp16 (2MB)

__device__ __forceinline__ uint32_t pack_h2(float lo, float hi) {
    __half2 h = __floats2half2_rn(lo, hi);
    return *reinterpret_cast<uint32_t*>(&h);
}
__device__ __forceinline__ float tanh_ap(float x) {
    float y;
    asm("tanh.approx.f32 %0, %1;" : "=f"(y) : "f"(x));
    return y;
}

// ===========================================================================
// Kernel 1 (prep): blocks 0..127 H' GEMM + zero g_z; rest convert to fp16.
// Conversion: 2 independent 8-float chunks per thread (4 in-flight float4
// loads) to push DRAM past the 55% latency limit seen in R8.
// ===========================================================================
#define H_BLOCKS 128
#define TCH (A_ELEMS / 8 + B_ELEMS / 8)          /* 3,342,336 chunks */
#define ACH (A_ELEMS / 8)
#define CONV_BLOCKS ((TCH + 511) / 512)          /* 6528 */

__device__ __forceinline__ void conv_chunk(long idx8,
                                           const float* __restrict__ A,
                                           const float* __restrict__ Bw,
                                           float4& v0, float4& v1)
{
    const float* src = (idx8 < ACH) ? (A + idx8 * 8) : (Bw + (idx8 - ACH) * 8);
    v0 = *reinterpret_cast<const float4*>(src);
    v1 = *reinterpret_cast<const float4*>(src + 4);
}
__device__ __forceinline__ void conv_store(long idx8, float4 v0, float4 v1)
{
    __half* dst = (idx8 < ACH) ? (g_Af16 + idx8 * 8) : (g_Bf16 + (idx8 - ACH) * 8);
    *reinterpret_cast<uint4*>(dst) =
        make_uint4(pack_h2(v0.x, v0.y), pack_h2(v0.z, v0.w),
                   pack_h2(v1.x, v1.y), pack_h2(v1.z, v1.w));
}

__global__ __launch_bounds__(256) void prep_kernel(
    const float* __restrict__ X,
    const float* __restrict__ W,
    const float* __restrict__ bl,
    const float* __restrict__ bc,
    const float* __restrict__ A,
    const float* __restrict__ Bw)
{
    __shared__ float As[32 * 129];
    __shared__ float Bs[32 * 129];
    const int t = threadIdx.x;

    if (blockIdx.x >= H_BLOCKS) {
        long base = (long)(blockIdx.x - H_BLOCKS) * 512 + t;
        long i0 = base, i1 = base + 256;
        float4 a0, a1, b0, b1;
        bool ok0 = i0 < TCH, ok1 = i1 < TCH;
        if (ok0) conv_chunk(i0, A, Bw, a0, a1);
        if (ok1) conv_chunk(i1, A, Bw, b0, b1);
        if (ok0) conv_store(i0, a0, a1);
        if (ok1) conv_store(i1, b0, b1);
        return;
    }

    // ---- H' GEMM (blocks 0..127) ----
    const int hb = blockIdx.x;
    const int mBase = (hb & 7) * 32;
    const int nBase = (hb >> 3) * 32;

    int flat = hb * 256 + t;
    if (flat < M_TOTAL) g_z[flat] = 0.0f;

    const int row = t >> 3;
    const int fc  = t & 7;
    const int ty  = t >> 4;
    const int tx  = t & 15;

    const float* xp = X + (size_t)(mBase + row) * LSTMH;
    const float* wp = W + (size_t)(nBase + row) * LSTMH;

    float acc[2][2] = {{0.f, 0.f}, {0.f, 0.f}};
    float4 pa[4], pb[4];

    #pragma unroll
    for (int i = 0; i < 4; i++) {
        pa[i] = *reinterpret_cast<const float4*>(xp + (fc + 8 * i) * 4);
        pb[i] = *reinterpret_cast<const float4*>(wp + (fc + 8 * i) * 4);
    }

    for (int c = 0; c < 4; c++) {
        if (c) __syncthreads();
        #pragma unroll
        for (int i = 0; i < 4; i++) {
            int base = row * 129 + (fc + 8 * i) * 4;
            As[base + 0] = pa[i].x; As[base + 1] = pa[i].y;
            As[base + 2] = pa[i].z; As[base + 3] = pa[i].w;
            Bs[base + 0] = pb[i].x; Bs[base + 1] = pb[i].y;
            Bs[base + 2] = pb[i].z; Bs[base + 3] = pb[i].w;
        }
        __syncthreads();
        if (c < 3) {
            int k0 = (c + 1) * 128;
            #pragma unroll
            for (int i = 0; i < 4; i++) {
                pa[i] = *reinterpret_cast<const float4*>(xp + k0 + (fc + 8 * i) * 4);
                pb[i] = *reinterpret_cast<const float4*>(wp + k0 + (fc + 8 * i) * 4);
            }
        }
        #pragma unroll 8
        for (int k = 0; k < 128; k++) {
            float a0 = As[(ty * 2 + 0) * 129 + k];
            float a1 = As[(ty * 2 + 1) * 129 + k];
            float b0 = Bs[(tx * 2 + 0) * 129 + k];
            float b1 = Bs[(tx * 2 + 1) * 129 + k];
            acc[0][0] += a0 * b0; acc[0][1] += a0 * b1;
            acc[1][0] += a1 * b0; acc[1][1] += a1 * b1;
        }
    }

    #pragma unroll
    for (int i = 0; i < 2; i++)
        #pragma unroll
        for (int j = 0; j < 2; j++) {
            int col = nBase + tx * 2 + j;
            g_H[(size_t)(mBase + ty * 2 + i) * PROJ + col] = acc[i][j] + bl[col] + bc[col];
        }
}

// ===========================================================================
// Kernel 2: fp16 mma m16n8k16, cp.async 3-slot ring, K-chunk 64 halves
// (128B rows, XOR SW128 swizzle, no padding). 32 stages, 1 barrier/stage.
// BM=BN=128, 8 warps (2M x 4N), warp tile 64x32, ldmatrix.x4.
// grid (4, 98): col tile fastest; A fp16 (51MB) is L2-resident.
// ===========================================================================
#define KCH    64                         /* halves per stage (128 B) */
#define NSTG   (CNNC / KCH)               /* 32 */
#define STG_B  (2 * 128 * 128)            /* A 16KB + B 16KB = 32768 */
#define NRING  3
#define ATT_SMEM (NRING * STG_B + 128)    /* + alignment slack */

__device__ __forceinline__ void ldsm_x4(uint32_t& r0, uint32_t& r1,
                                        uint32_t& r2, uint32_t& r3, uint32_t addr)
{
    asm volatile("ldmatrix.sync.aligned.m8n8.x4.shared.b16 {%0,%1,%2,%3}, [%4];"
                 : "=r"(r0), "=r"(r1), "=r"(r2), "=r"(r3) : "r"(addr));
}
__device__ __forceinline__ void mma_f16(float c[4], const uint32_t a[4], const uint32_t b[2])
{
    asm volatile(
        "mma.sync.aligned.m16n8k16.row.col.f32.f16.f16.f32 "
        "{%0,%1,%2,%3}, {%4,%5,%6,%7}, {%8,%9}, {%0,%1,%2,%3};"
        : "+f"(c[0]), "+f"(c[1]), "+f"(c[2]), "+f"(c[3])
        : "r"(a[0]), "r"(a[1]), "r"(a[2]), "r"(a[3]), "r"(b[0]), "r"(b[1]));
}
__device__ __forceinline__ void cp_async16(uint32_t sdst, const void* gsrc) {
    asm volatile("cp.async.cg.shared.global [%0], [%1], 16;" :: "r"(sdst), "l"(gsrc) : "memory");
}
__device__ __forceinline__ void cp_commit() { asm volatile("cp.async.commit_group;" ::: "memory"); }
__device__ __forceinline__ void cp_wait1()  { asm volatile("cp.async.wait_group 1;"  ::: "memory"); }

__global__ __launch_bounds__(256, 2) void attn_gemm_kernel(
    const float* __restrict__ w_attn)
{
    extern __shared__ __align__(128) char smem[];
    const uint32_t sb = ((uint32_t)__cvta_generic_to_shared(smem) + 127u) & ~127u;

    const int t       = threadIdx.x;
    const int lane    = t & 31;
    const int wid     = t >> 5;
    const int warpM   = wid >> 2;           // 0..1
    const int warpN   = wid & 3;            // 0..3
    const int colBase = blockIdx.x * 128;   // 4 (fastest)
    const int rowBase = blockIdx.y * 128;   // 98

    // ldmatrix lane bases. Swizzled addr = rowBase128 + (kx ^ rx),
    // kx = ks*32 + kq (0..127), rx = (row&7)*16.
    uint32_t baseA[4], rxA[4];
    const uint32_t kqA = (uint32_t)(((lane >> 4) & 1) * 16);
    #pragma unroll
    for (int mi = 0; mi < 4; mi++) {
        int r = warpM * 64 + mi * 16 + (lane & 15);
        baseA[mi] = (uint32_t)(r * 128);
        rxA[mi]   = (uint32_t)((r & 7) * 16);
    }
    uint32_t baseB[2], rxB[2];
    const uint32_t kqB = (uint32_t)(((lane >> 3) & 1) * 16);
    #pragma unroll
    for (int np = 0; np < 2; np++) {
        int r = warpN * 32 + np * 16 + ((lane >> 4) & 1) * 8 + (lane & 7);
        baseB[np] = (uint32_t)(r * 128);
        rxB[np]   = (uint32_t)((r & 7) * 16);
    }

    float acc[4][4][4];
    #pragma unroll
    for (int mi = 0; mi < 4; mi++)
        #pragma unroll
        for (int ni = 0; ni < 4; ni++)
            #pragma unroll
            for (int c = 0; c < 4; c++) acc[mi][ni][c] = 0.0f;

    // Loader: 1024 16B-chunks each for A and B per stage; thread does 4+4.
    // chunk c: row=c>>3, ch=c&7; consecutive t -> consecutive ch (coalesced).
    const __half* gA = g_Af16 + (size_t)rowBase * CNNC;
    const __half* gB = g_Bf16 + (size_t)colBase * CNNC;

    auto load_stage = [&](int slot, int kt) {
        const uint32_t aDst = sb + slot * STG_B;
        const uint32_t bDst = aDst + 128 * 128;
        const int kOff = kt * KCH;
        #pragma unroll
        for (int j = 0; j < 4; j++) {
            int c   = t + 256 * j;          // 0..1023
            int row = c >> 3;
            int ch  = c & 7;
            uint32_t x = (uint32_t)(ch * 16) ^ (uint32_t)((row & 7) * 16);
            uint32_t d = (uint32_t)(row * 128) + x;
            cp_async16(aDst + d, gA + (size_t)row * CNNC + kOff + ch * 8);
            cp_async16(bDst + d, gB + (size_t)row * CNNC + kOff + ch * 8);
        }
    };

    load_stage(0, 0); cp_commit();
    load_stage(1, 1); cp_commit();

    for (int kt = 0; kt < NSTG; kt++) {
        cp_wait1();
        __syncthreads();

        if (kt + 2 < NSTG) load_stage((kt + 2) % NRING, kt + 2);
        cp_commit();

        const uint32_t aBase = sb + (kt % NRING) * STG_B;
        const uint32_t bBase = aBase + 128 * 128;
        #pragma unroll
        for (int ks = 0; ks < 4; ks++) {
            const uint32_t kxA = (uint32_t)(ks * 32) + kqA;
            const uint32_t kxB = (uint32_t)(ks * 32) + kqB;
            uint32_t af[4][4];
            uint32_t bf[4][2];
            #pragma unroll
            for (int mi = 0; mi < 4; mi++)
                ldsm_x4(af[mi][0], af[mi][1], af[mi][2], af[mi][3],
                        aBase + baseA[mi] + (kxA ^ rxA[mi]));
            #pragma unroll
            for (int np = 0; np < 2; np++) {
                uint32_t r0, r1, r2, r3;
                ldsm_x4(r0, r1, r2, r3, bBase + baseB[np] + (kxB ^ rxB[np]));
                bf[np * 2 + 0][0] = r0; bf[np * 2 + 0][1] = r1;
                bf[np * 2 + 1][0] = r2; bf[np * 2 + 1][1] = r3;
            }
            #pragma unroll
            for (int mi = 0; mi < 4; mi++)
                #pragma unroll
                for (int ni = 0; ni < 4; ni++)
                    mma_f16(acc[mi][ni], af[mi], bf[ni]);
        }
    }

    // Epilogue: z[r] += sum_p tanh(V[r,p] + H'[b,p]) * w_attn[p]
    const int tig = lane & 3;
    const float* wcol = w_attn + colBase + warpN * 32;
    #pragma unroll
    for (int mi = 0; mi < 4; mi++) {
        #pragma unroll
        for (int h = 0; h < 2; h++) {
            int r = rowBase + warpM * 64 + mi * 16 + h * 8 + (lane >> 2);
            int bidx = r / GRID_G;
            const float* Hrow = g_H + (size_t)bidx * PROJ + colBase + warpN * 32;
            float s = 0.0f;
            #pragma unroll
            for (int ni = 0; ni < 4; ni++) {
                int p = ni * 8 + tig * 2;
                float v0 = acc[mi][ni][h * 2 + 0] + __ldg(Hrow + p);
                float v1 = acc[mi][ni][h * 2 + 1] + __ldg(Hrow + p + 1);
                s += tanh_ap(v0) * __ldg(wcol + p) + tanh_ap(v1) * __ldg(wcol + p + 1);
            }
            s += __shfl_xor_sync(0xffffffffu, s, 1);
            s += __shfl_xor_sync(0xffffffffu, s, 2);
            if (tig == 0) atomicAdd(&g_z[r], s);
        }
    }
}

// ===========================================================================
// Kernel 3: scramble + row softmax
// ===========================================================================
__global__ __launch_bounds__(64) void softmax_kernel(float* __restrict__ out)
{
    __shared__ float red[64];
    const int i = blockIdx.x;
    const int t = threadIdx.x;

    float v = -INFINITY;
    if (t < GRID_G) {
        int k = i * GRID_G + t;
        v = g_z[(k % BSZ) * GRID_G + (k / BSZ)];
    }
    red[t] = v;
    __syncthreads();
    #pragma unroll
    for (int s = 32; s > 0; s >>= 1) {
        if (t < s) red[t] = fmaxf(red[t], red[t + s]);
        __syncthreads();
    }
    float mx = red[0];
    __syncthreads();

    float e = (t < GRID_G) ? expf(v - mx) : 0.0f;
    red[t] = e;
    __syncthreads();
    #pragma unroll
    for (int s = 32; s > 0; s >>= 1) {
        if (t < s) red[t] += red[t + s];
        __syncthreads();
    }
    float sum = red[0];
    if (t < GRID_G) out[i * GRID_G + t] = e / sum;
}

// ===========================================================================
extern "C" void kernel_launch(void* const* d_in, const int* in_sizes, int n_in,
                              void* d_out, int out_size)
{
    const float* lstm = (const float*)d_in[0];
    const float* cnn  = (const float*)d_in[1];
    const float* Wl   = (const float*)d_in[2];
    const float* bl   = (const float*)d_in[3];
    const float* Wc   = (const float*)d_in[4];
    const float* bc   = (const float*)d_in[5];
    const float* wa   = (const float*)d_in[6];
    float* out = (float*)d_out;

    cudaFuncSetAttribute(attn_gemm_kernel,
                         cudaFuncAttributeMaxDynamicSharedMemorySize, ATT_SMEM);

    prep_kernel<<<H_BLOCKS + CONV_BLOCKS, 256>>>(lstm, Wl, bl, bc, cnn, Wc);
    attn_gemm_kernel<<<dim3(4, 98), 256, ATT_SMEM>>>(wa);
    softmax_kernel<<<256, 64>>>(out);
}